// round 3
// baseline (speedup 1.0000x reference)
#include <cuda_runtime.h>
#include <math.h>

#define VN    8192            // 2N
#define NHALF 4096            // N
#define NCOL  64              // B*C = 4*16
#define BM    128
#define BK    32
#define SPLITK 4
#define KSPAN (VN / SPLITK)   // 2048

typedef unsigned long long ull;

// ---------------- device scratch (no runtime allocation allowed) -------------
__device__ float g_adj[(size_t)VN * VN];                 // 256 MB raw blended adj
__device__ float g_rowsum[VN];
__device__ float g_part[SPLITK][(size_t)VN * NCOL];      // split-K partial dots
__device__ float g_rspart[SPLITK][VN];                   // split-K partial rowsums
__device__ float g_X[2][(size_t)VN * NCOL];              // ping-pong hop vectors [v][col]
__device__ float g_w4[4];                                // softmax(alpha) weights
__device__ float g_s1[128 * 128];                        // BN partial sums  [blk][o]
__device__ float g_s2[128 * 128];                        // BN partial sumsq [blk][o]
__device__ float g_mu[128];
__device__ float g_rstd[128];

// ---------------- f32x2 packed-FMA helpers (sm_100+) ------------------------
__device__ __forceinline__ ull pk2(float lo, float hi) {
    ull r; asm("mov.b64 %0, {%1,%2};" : "=l"(r) : "f"(lo), "f"(hi)); return r;
}
__device__ __forceinline__ void fma2(ull& d, ull a, ull b) {
    asm("fma.rn.f32x2 %0, %1, %2, %0;" : "+l"(d) : "l"(a), "l"(b));
}
__device__ __forceinline__ float2 upk2(ull v) {
    float lo, hi; asm("mov.b64 {%0,%1}, %2;" : "=f"(lo), "=f"(hi) : "l"(v));
    float2 r; r.x = lo; r.y = hi; return r;
}

// ---------------- tiny: softmax of the 2-element alphas ---------------------
__global__ void k_alpha(const float* __restrict__ af, const float* __restrict__ as) {
    float e0 = expf(af[0]), e1 = expf(af[1]);
    g_w4[0] = e0 / (e0 + e1); g_w4[1] = e1 / (e0 + e1);
    float f0 = expf(as[0]), f1 = expf(as[1]);
    g_w4[2] = f0 / (f0 + f1); g_w4[3] = f1 / (f0 + f1);
}

// ---------------- K1: fused blend + store raw adj + rowsum + hop-1 GEMM -----
// grid (VN/BM, SPLITK), 256 threads. Each thread: 8 rows x 4 cols micro-tile.
__global__ __launch_bounds__(256, 2) void k_hop1(
    const float* __restrict__ adjf, const float* __restrict__ adjsec,
    const float* __restrict__ adjm, const float* __restrict__ data)
{
    __shared__ float adjS[BK][BM + 4];   // [k][row]
    __shared__ float Xs[BK][NCOL + 4];   // [k][col]

    const int tid   = threadIdx.x;
    const int vbase = blockIdx.x * BM;
    const int s     = blockIdx.y;
    const int kbase = s * KSPAN;

    const float w0 = g_w4[0], w1 = g_w4[1], w2 = g_w4[2], w3 = g_w4[3];

    const int rowg = tid >> 4, colg = tid & 15;
    const int r0 = rowg * 8, c0 = colg * 4;
    const int srow = tid >> 3;             // 0..31
    const int skk  = (tid & 7) << 2;       // 0,4,...,28

    const float* __restrict__ pf1 = adjf   + (size_t)VN * VN;
    const float* __restrict__ ps1 = adjsec + (size_t)VN * VN;

    ull acc[8][2];
#pragma unroll
    for (int i = 0; i < 8; ++i) { acc[i][0] = 0ULL; acc[i][1] = 0ULL; }
    float rsp[4] = {0.f, 0.f, 0.f, 0.f};

    for (int kt = 0; kt < KSPAN; kt += BK) {
        const int kg = kbase + kt;
        __syncthreads();
        // stage + blend adj tile (128 rows x 32 k), write raw adj to global
#pragma unroll
        for (int p = 0; p < 4; ++p) {
            const int row = p * 32 + srow;
            const size_t off = (size_t)(vbase + row) * VN + kg + skk;
            float4 a = *(const float4*)(adjf   + off);
            float4 b = *(const float4*)(pf1    + off);
            float4 c = *(const float4*)(adjsec + off);
            float4 d = *(const float4*)(ps1    + off);
            float4 m = *(const float4*)(adjm   + off);
            float4 r;
            r.x = fmaf(w0, a.x, fmaf(w1, b.x, fmaf(w2, c.x, fmaf(w3, d.x, m.x))));
            r.y = fmaf(w0, a.y, fmaf(w1, b.y, fmaf(w2, c.y, fmaf(w3, d.y, m.y))));
            r.z = fmaf(w0, a.z, fmaf(w1, b.z, fmaf(w2, c.z, fmaf(w3, d.z, m.z))));
            r.w = fmaf(w0, a.w, fmaf(w1, b.w, fmaf(w2, c.w, fmaf(w3, d.w, m.w))));
            *(float4*)(g_adj + off) = r;
            adjS[skk + 0][row] = r.x; adjS[skk + 1][row] = r.y;
            adjS[skk + 2][row] = r.z; adjS[skk + 3][row] = r.w;
            rsp[p] += (r.x + r.y) + (r.z + r.w);
        }
        // stage X0 tile transposed: data[col][w] -> Xs[k][col]
#pragma unroll
        for (int p = 0; p < 2; ++p) {
            const int idx = tid + p * 256;
            const int col = idx >> 3;
            const int kk  = (idx & 7) << 2;
            float4 x = *(const float4*)(data + (size_t)col * 16384 + kg + kk);
            Xs[kk + 0][col] = x.x; Xs[kk + 1][col] = x.y;
            Xs[kk + 2][col] = x.z; Xs[kk + 3][col] = x.w;
        }
        __syncthreads();
        // micro-kernel: 8 rows x 4 cols, f32x2 packed on column pairs
#pragma unroll
        for (int k = 0; k < BK; ++k) {
            float4 a03 = *(const float4*)&adjS[k][r0];
            float4 a47 = *(const float4*)&adjS[k][r0 + 4];
            float4 xv  = *(const float4*)&Xs[k][c0];
            ull x01 = pk2(xv.x, xv.y), x23 = pk2(xv.z, xv.w);
            float av[8] = {a03.x, a03.y, a03.z, a03.w, a47.x, a47.y, a47.z, a47.w};
#pragma unroll
            for (int i = 0; i < 8; ++i) {
                ull aa = pk2(av[i], av[i]);
                fma2(acc[i][0], aa, x01);
                fma2(acc[i][1], aa, x23);
            }
        }
    }
    // partial dot products
#pragma unroll
    for (int i = 0; i < 8; ++i) {
        float2 lo = upk2(acc[i][0]), hi = upk2(acc[i][1]);
        float4 o; o.x = lo.x; o.y = lo.y; o.z = hi.x; o.w = hi.y;
        *(float4*)(&g_part[s][(size_t)(vbase + r0 + i) * NCOL + c0]) = o;
    }
    // partial rowsums: 8 lanes share a row (same tid>>3 within warp)
#pragma unroll
    for (int p = 0; p < 4; ++p) {
        float v = rsp[p];
        v += __shfl_xor_sync(0xffffffffu, v, 1);
        v += __shfl_xor_sync(0xffffffffu, v, 2);
        v += __shfl_xor_sync(0xffffffffu, v, 4);
        if ((tid & 7) == 0)
            g_rspart[s][vbase + p * 32 + srow] = v;
    }
}

// ---------------- K2: hop GEMM from materialized raw adj --------------------
__global__ __launch_bounds__(256, 2) void k_hop(int srcSel)
{
    __shared__ float adjS[BK][BM + 4];
    __shared__ float Xs[BK][NCOL + 4];

    const int tid   = threadIdx.x;
    const int vbase = blockIdx.x * BM;
    const int s     = blockIdx.y;
    const int kbase = s * KSPAN;
    const int rowg = tid >> 4, colg = tid & 15;
    const int r0 = rowg * 8, c0 = colg * 4;
    const int srow = tid >> 3;
    const int skk  = (tid & 7) << 2;
    const float* __restrict__ Xsrc = g_X[srcSel];

    ull acc[8][2];
#pragma unroll
    for (int i = 0; i < 8; ++i) { acc[i][0] = 0ULL; acc[i][1] = 0ULL; }

    for (int kt = 0; kt < KSPAN; kt += BK) {
        const int kg = kbase + kt;
        __syncthreads();
#pragma unroll
        for (int p = 0; p < 4; ++p) {
            const int row = p * 32 + srow;
            const size_t off = (size_t)(vbase + row) * VN + kg + skk;
            float4 r = *(const float4*)(g_adj + off);
            adjS[skk + 0][row] = r.x; adjS[skk + 1][row] = r.y;
            adjS[skk + 2][row] = r.z; adjS[skk + 3][row] = r.w;
        }
        // X already [w][col]: direct coalesced float4 into Xs[k][col]
#pragma unroll
        for (int p = 0; p < 2; ++p) {
            const int idx = tid + p * 256;
            const int k  = idx >> 4;
            const int c4 = (idx & 15) << 2;
            *(float4*)&Xs[k][c4] = *(const float4*)(Xsrc + (size_t)(kg + k) * NCOL + c4);
        }
        __syncthreads();
#pragma unroll
        for (int k = 0; k < BK; ++k) {
            float4 a03 = *(const float4*)&adjS[k][r0];
            float4 a47 = *(const float4*)&adjS[k][r0 + 4];
            float4 xv  = *(const float4*)&Xs[k][c0];
            ull x01 = pk2(xv.x, xv.y), x23 = pk2(xv.z, xv.w);
            float av[8] = {a03.x, a03.y, a03.z, a03.w, a47.x, a47.y, a47.z, a47.w};
#pragma unroll
            for (int i = 0; i < 8; ++i) {
                ull aa = pk2(av[i], av[i]);
                fma2(acc[i][0], aa, x01);
                fma2(acc[i][1], aa, x23);
            }
        }
    }
#pragma unroll
    for (int i = 0; i < 8; ++i) {
        float2 lo = upk2(acc[i][0]), hi = upk2(acc[i][1]);
        float4 o; o.x = lo.x; o.y = lo.y; o.z = hi.x; o.w = hi.y;
        *(float4*)(&g_part[s][(size_t)(vbase + r0 + i) * NCOL + c0]) = o;
    }
}

// ---------------- split-K reductions -----------------------------------------
__global__ void k_combine1() {   // also finalizes rowsum; divides by it
    const int idx = blockIdx.x * 256 + threadIdx.x;
    const int v = idx >> 6;
    float sum = g_part[0][idx] + g_part[1][idx] + g_part[2][idx] + g_part[3][idx];
    float rs  = g_rspart[0][v] + g_rspart[1][v] + g_rspart[2][v] + g_rspart[3][v];
    g_X[0][idx] = sum / rs;
    if ((idx & 63) == 0) g_rowsum[v] = rs;
}

__global__ void k_combine(int dstSel) {
    const int idx = blockIdx.x * 256 + threadIdx.x;
    const int v = idx >> 6;
    float sum = g_part[0][idx] + g_part[1][idx] + g_part[2][idx] + g_part[3][idx];
    g_X[dstSel][idx] = sum / g_rowsum[v];
}

// ---------------- BN stats: per-block partial sums over (b,n) ---------------
// point q in [0,16384): x values are contiguous: X[262144 + 16q + c]
__global__ __launch_bounds__(128) void k_stats(int sel, const float* __restrict__ W,
                                               const float* __restrict__ bias)
{
    __shared__ float xs[2048];
    const int tid = threadIdx.x;   // channel o
    const float* __restrict__ Xsrc = g_X[sel] + (size_t)NHALF * NCOL;
    const int q0 = blockIdx.x * 128;
#pragma unroll
    for (int j = 0; j < 4; ++j)
        *(float4*)&xs[tid * 16 + j * 4] =
            *(const float4*)(Xsrc + (size_t)q0 * 16 + tid * 16 + j * 4);
    __syncthreads();
    float w[16];
#pragma unroll
    for (int c = 0; c < 16; ++c) w[c] = W[tid * 16 + c];
    const float bb = bias[tid];
    float s = 0.f, ss = 0.f;
    for (int q = 0; q < 128; ++q) {
        const float* xq = &xs[q * 16];
        float y = bb;
#pragma unroll
        for (int c = 0; c < 16; ++c) y = fmaf(w[c], xq[c], y);
        s += y;
        ss = fmaf(y, y, ss);
    }
    g_s1[blockIdx.x * 128 + tid] = s;
    g_s2[blockIdx.x * 128 + tid] = ss;
}

__global__ void k_stats2() {
    const int o = threadIdx.x;
    float s = 0.f, ss = 0.f;
    for (int b2 = 0; b2 < 128; ++b2) { s += g_s1[b2 * 128 + o]; ss += g_s2[b2 * 128 + o]; }
    const float inv = 1.f / 16384.f;
    float mu = s * inv;
    float var = ss * inv - mu * mu;
    g_mu[o] = mu;
    g_rstd[o] = rsqrtf(var + 1e-5f);
}

// ---------------- GLU + BN apply + running max into output -------------------
// grid (32, 4): blockIdx.x -> n tile, blockIdx.y -> batch b; 128 threads over n
__global__ __launch_bounds__(128) void k_glu(int sel, const float* __restrict__ W,
    const float* __restrict__ bias, const float* __restrict__ gamma,
    const float* __restrict__ beta, float* __restrict__ out, int first)
{
    __shared__ float Wsm[2048], bsm[128], gsm[128], besm[128], musm[128], rsm[128];
    const int tid = threadIdx.x;
    const int n = blockIdx.x * 128 + tid;
    const int b = blockIdx.y;
#pragma unroll
    for (int j = 0; j < 16; ++j) Wsm[tid * 16 + j] = W[tid * 16 + j];
    bsm[tid] = bias[tid]; gsm[tid] = gamma[tid]; besm[tid] = beta[tid];
    musm[tid] = g_mu[tid]; rsm[tid] = g_rstd[tid];
    __syncthreads();

    float xr[16];
    const float* __restrict__ xp =
        g_X[sel] + (size_t)NHALF * NCOL + (size_t)n * 64 + b * 16;
#pragma unroll
    for (int j = 0; j < 4; ++j) {
        float4 t = *(const float4*)(xp + j * 4);
        xr[j * 4 + 0] = t.x; xr[j * 4 + 1] = t.y; xr[j * 4 + 2] = t.z; xr[j * 4 + 3] = t.w;
    }
    float* op = out + (size_t)b * (64 * 4096) + n;
    for (int f = 0; f < 64; ++f) {
        const float* wl = &Wsm[f * 16];
        const float* wr = &Wsm[(f + 64) * 16];
        float yl = bsm[f], yr = bsm[f + 64];
#pragma unroll
        for (int c = 0; c < 16; ++c) {
            yl = fmaf(wl[c], xr[c], yl);
            yr = fmaf(wr[c], xr[c], yr);
        }
        yl = fmaf(gsm[f]      * (yl - musm[f]),      rsm[f],      besm[f]);
        yr = fmaf(gsm[f + 64] * (yr - musm[f + 64]), rsm[f + 64], besm[f + 64]);
        float val = yl / (1.f + expf(-yr));
        float* po = op + (size_t)f * 4096;
        if (first) *po = val;
        else       *po = fmaxf(*po, val);
    }
}

// ---------------- launch -----------------------------------------------------
extern "C" void kernel_launch(void* const* d_in, const int* in_sizes, int n_in,
                              void* d_out, int out_size)
{
    (void)in_sizes; (void)n_in; (void)out_size;
    const float* adjf = (const float*)d_in[0];
    const float* adjs = (const float*)d_in[1];
    const float* adjm = (const float*)d_in[2];
    const float* data = (const float*)d_in[3];
    const float* alf  = (const float*)d_in[4];
    const float* als  = (const float*)d_in[5];
    const float* gw   = (const float*)d_in[6];
    const float* gb   = (const float*)d_in[7];
    const float* gg   = (const float*)d_in[8];
    const float* gbe  = (const float*)d_in[9];
    float* out = (float*)d_out;

    k_alpha<<<1, 1>>>(alf, als);

    dim3 gemmGrid(VN / BM, SPLITK);
    k_hop1<<<gemmGrid, 256>>>(adjf, adjs, adjm, data);
    k_combine1<<<(VN * NCOL) / 256, 256>>>();

    int src = 0;
    for (int h = 0; h < 3; ++h) {
        k_stats<<<128, 128>>>(src, gw + h * 2048, gb + h * 128);
        k_stats2<<<1, 128>>>();
        k_glu<<<dim3(32, 4), 128>>>(src, gw + h * 2048, gb + h * 128,
                                    gg + h * 128, gbe + h * 128, out, h == 0 ? 1 : 0);
        if (h < 2) {
            k_hop<<<gemmGrid, 256>>>(src);
            k_combine<<<(VN * NCOL) / 256, 256>>>(1 - src);
            src = 1 - src;
        }
    }
}

// round 6
// speedup vs baseline: 1.3613x; 1.3613x over previous
#include <cuda_runtime.h>
#include <cuda_bf16.h>
#include <math.h>
#include <stdint.h>

#define VN    8192
#define NCOL  64
#define KT    64            // k-tile
#define KA    72            // padded smem stride (bf16 units)
#define NT    64            // tiles per CTA = KSPAN/KT
#define KSPAN 4096          // split-K = 2

// smem plane byte offsets within one buffer
#define APLANE 18432        // 128 * 72 * 2
#define BPLANE 9216         // 64 * 72 * 2
#define AHI 0
#define ALO APLANE
#define BHI (2*APLANE)
#define BLO (2*APLANE + BPLANE)
#define BUFSZ (2*APLANE + 2*BPLANE)   // 55296
#define DSMEM (2*BUFSZ)               // 110592

// ---------------- device scratch ---------------------------------------------
__device__ float g_adj[(size_t)VN * VN];          // 256 MB blended adj (un-normalized)
__device__ float g_rowsum[VN];
__device__ float g_part[2][(size_t)VN * NCOL];    // split-K partials
__device__ float g_X[(size_t)VN * NCOL];          // hop output, [v][col]
__device__ float g_XT[(size_t)NCOL * VN];         // hop output transposed [col][w]
__device__ float g_w4[4];
__device__ float g_s1[256 * 128];
__device__ float g_s2[256 * 128];
__device__ float g_mu[128];
__device__ float g_rstd[128];

// ---------------- helpers ------------------------------------------------------
__device__ __forceinline__ void bsplit(float x, float y, uint32_t& hi, uint32_t& lo) {
    __nv_bfloat162 h = __floats2bfloat162_rn(x, y);
    float hx = __bfloat162float(h.x), hy = __bfloat162float(h.y);
    __nv_bfloat162 l = __floats2bfloat162_rn(x - hx, y - hy);
    hi = *reinterpret_cast<uint32_t*>(&h);
    lo = *reinterpret_cast<uint32_t*>(&l);
}

__device__ __forceinline__ void mma_bf16(float* c,
    uint32_t a0, uint32_t a1, uint32_t a2, uint32_t a3, uint32_t b0, uint32_t b1) {
    asm volatile(
        "mma.sync.aligned.m16n8k16.row.col.f32.bf16.bf16.f32 "
        "{%0,%1,%2,%3}, {%4,%5,%6,%7}, {%8,%9}, {%0,%1,%2,%3};"
        : "+f"(c[0]), "+f"(c[1]), "+f"(c[2]), "+f"(c[3])
        : "r"(a0), "r"(a1), "r"(a2), "r"(a3), "r"(b0), "r"(b1));
}

// ---------------- alpha softmax ----------------------------------------------
__global__ void k_alpha(const float* __restrict__ af, const float* __restrict__ as) {
    float e0 = expf(af[0]), e1 = expf(af[1]);
    g_w4[0] = e0 / (e0 + e1); g_w4[1] = e1 / (e0 + e1);
    float f0 = expf(as[0]), f1 = expf(as[1]);
    g_w4[2] = f0 / (f0 + f1); g_w4[3] = f1 / (f0 + f1);
}

// ---------------- blend: 5-stream -> g_adj + deterministic rowsum ------------
__global__ __launch_bounds__(256) void k_blend(
    const float* __restrict__ adjf, const float* __restrict__ adjs,
    const float* __restrict__ adjm)
{
    const int wid = threadIdx.x >> 5, lane = threadIdx.x & 31;
    const int row = blockIdx.x * 8 + wid;
    const size_t base = (size_t)row * VN;
    const float w0 = g_w4[0], w1 = g_w4[1], w2 = g_w4[2], w3 = g_w4[3];
    const float* __restrict__ a0 = adjf + base;
    const float* __restrict__ a1 = adjf + (size_t)VN * VN + base;
    const float* __restrict__ b0 = adjs + base;
    const float* __restrict__ b1 = adjs + (size_t)VN * VN + base;
    const float* __restrict__ m0 = adjm + base;
    float* __restrict__ dst = g_adj + base;
    float rs = 0.f;
    for (int i = lane; i < 2048; i += 64) {
#pragma unroll
        for (int u = 0; u < 2; ++u) {
            const int o4 = (i + u * 32) * 4;
            float4 a = *(const float4*)(a0 + o4);
            float4 b = *(const float4*)(a1 + o4);
            float4 c = *(const float4*)(b0 + o4);
            float4 d = *(const float4*)(b1 + o4);
            float4 m = *(const float4*)(m0 + o4);
            float4 r;
            r.x = fmaf(w0, a.x, fmaf(w1, b.x, fmaf(w2, c.x, fmaf(w3, d.x, m.x))));
            r.y = fmaf(w0, a.y, fmaf(w1, b.y, fmaf(w2, c.y, fmaf(w3, d.y, m.y))));
            r.z = fmaf(w0, a.z, fmaf(w1, b.z, fmaf(w2, c.z, fmaf(w3, d.z, m.z))));
            r.w = fmaf(w0, a.w, fmaf(w1, b.w, fmaf(w2, c.w, fmaf(w3, d.w, m.w))));
            *(float4*)(dst + o4) = r;
            rs += (r.x + r.y) + (r.z + r.w);
        }
    }
    rs += __shfl_xor_sync(0xffffffffu, rs, 16);
    rs += __shfl_xor_sync(0xffffffffu, rs, 8);
    rs += __shfl_xor_sync(0xffffffffu, rs, 4);
    rs += __shfl_xor_sync(0xffffffffu, rs, 2);
    rs += __shfl_xor_sync(0xffffffffu, rs, 1);
    if (lane == 0) g_rowsum[row] = rs;
}

// ---------------- tensor GEMM via mma.sync bf16 3-split -----------------------
// P[v, col] = sum_w adj[v, w] * B[col, w]
// useData=1: B = data (stride 16384); else B = g_XT (stride VN).
// grid (64, 2): 128-row M tiles x split-K. 256 thr = 8 warps, warp = 16 rows x 64 cols.
__global__ __launch_bounds__(256, 1) void k_gemm(const float* __restrict__ data, int useData)
{
    extern __shared__ __align__(16) char smem[];
    const int tid = threadIdx.x, lane = tid & 31, wid = tid >> 5;
    const int vbase = blockIdx.x * 128;
    const int kbase = blockIdx.y * KSPAN;
    const float* __restrict__ Ab = g_adj + (size_t)vbase * VN + kbase;
    const float* __restrict__ Bb = (useData ? data : (const float*)g_XT) + kbase;
    const int bstride = useData ? 16384 : VN;

    const int wrow = wid * 16;
    const int gr = lane >> 2;            // 0..7
    const int qk = (lane & 3) * 2;       // 0,2,4,6

    float acc[8][4];
#pragma unroll
    for (int i = 0; i < 8; ++i)
#pragma unroll
        for (int j = 0; j < 4; ++j) acc[i][j] = 0.f;

    // prefetch tile 0 into registers
    float4 aR[8], bR[4];
#pragma unroll
    for (int j = 0; j < 8; ++j) {
        const int id = tid + j * 256, row = id >> 4, c4 = (id & 15) << 2;
        aR[j] = *(const float4*)(Ab + (size_t)row * VN + c4);
    }
#pragma unroll
    for (int j = 0; j < 4; ++j) {
        const int id = tid + j * 256, row = id >> 4, c4 = (id & 15) << 2;
        bR[j] = *(const float4*)(Bb + (size_t)row * bstride + c4);
    }

    for (int t = 0; t < NT; ++t) {
        char* bb = smem + (t & 1) * BUFSZ;
        // convert + stage tile t
#pragma unroll
        for (int j = 0; j < 8; ++j) {
            const int id = tid + j * 256, row = id >> 4, c4 = (id & 15) << 2;
            float4 v = aR[j];
            uint32_t h0, l0, h1, l1;
            bsplit(v.x, v.y, h0, l0);
            bsplit(v.z, v.w, h1, l1);
            const int bo = (row * KA + c4) * 2;
            *(uint2*)(bb + AHI + bo) = make_uint2(h0, h1);
            *(uint2*)(bb + ALO + bo) = make_uint2(l0, l1);
        }
#pragma unroll
        for (int j = 0; j < 4; ++j) {
            const int id = tid + j * 256, row = id >> 4, c4 = (id & 15) << 2;
            float4 v = bR[j];
            uint32_t h0, l0, h1, l1;
            bsplit(v.x, v.y, h0, l0);
            bsplit(v.z, v.w, h1, l1);
            const int bo = (row * KA + c4) * 2;
            *(uint2*)(bb + BHI + bo) = make_uint2(h0, h1);
            *(uint2*)(bb + BLO + bo) = make_uint2(l0, l1);
        }
        __syncthreads();
        // prefetch tile t+1 (overlaps with mma below)
        if (t + 1 < NT) {
            const int kg = (t + 1) * KT;
#pragma unroll
            for (int j = 0; j < 8; ++j) {
                const int id = tid + j * 256, row = id >> 4, c4 = (id & 15) << 2;
                aR[j] = *(const float4*)(Ab + (size_t)row * VN + kg + c4);
            }
#pragma unroll
            for (int j = 0; j < 4; ++j) {
                const int id = tid + j * 256, row = id >> 4, c4 = (id & 15) << 2;
                bR[j] = *(const float4*)(Bb + (size_t)row * bstride + kg + c4);
            }
        }
        // compute 4 k-steps of 16
        const char* Ah = bb + AHI;
        const char* Al = bb + ALO;
        const char* Bh = bb + BHI;
        const char* Bl = bb + BLO;
#pragma unroll
        for (int ks = 0; ks < 4; ++ks) {
            const int ko = ks * 16;
            const int rA = wrow + gr;
            uint32_t ah0 = *(const uint32_t*)(Ah + ((rA)     * KA + qk + ko) * 2);
            uint32_t ah1 = *(const uint32_t*)(Ah + ((rA + 8) * KA + qk + ko) * 2);
            uint32_t ah2 = *(const uint32_t*)(Ah + ((rA)     * KA + qk + 8 + ko) * 2);
            uint32_t ah3 = *(const uint32_t*)(Ah + ((rA + 8) * KA + qk + 8 + ko) * 2);
            uint32_t al0 = *(const uint32_t*)(Al + ((rA)     * KA + qk + ko) * 2);
            uint32_t al1 = *(const uint32_t*)(Al + ((rA + 8) * KA + qk + ko) * 2);
            uint32_t al2 = *(const uint32_t*)(Al + ((rA)     * KA + qk + 8 + ko) * 2);
            uint32_t al3 = *(const uint32_t*)(Al + ((rA + 8) * KA + qk + 8 + ko) * 2);
#pragma unroll
            for (int nb = 0; nb < 8; ++nb) {
                const int n = gr + nb * 8;
                uint32_t bh0 = *(const uint32_t*)(Bh + (n * KA + qk + ko) * 2);
                uint32_t bh1 = *(const uint32_t*)(Bh + (n * KA + qk + 8 + ko) * 2);
                uint32_t bl0 = *(const uint32_t*)(Bl + (n * KA + qk + ko) * 2);
                uint32_t bl1 = *(const uint32_t*)(Bl + (n * KA + qk + 8 + ko) * 2);
                mma_bf16(acc[nb], ah0, ah1, ah2, ah3, bh0, bh1);
                mma_bf16(acc[nb], ah0, ah1, ah2, ah3, bl0, bl1);
                mma_bf16(acc[nb], al0, al1, al2, al3, bh0, bh1);
            }
        }
        __syncthreads();
    }

    // epilogue: write partials
    float* dst = g_part[blockIdx.y] + (size_t)(vbase + wrow) * NCOL;
    const int cq = (lane & 3) * 2;
#pragma unroll
    for (int nb = 0; nb < 8; ++nb) {
        const int col = nb * 8 + cq;
        *(float2*)(dst + (size_t)gr * NCOL + col)       = make_float2(acc[nb][0], acc[nb][1]);
        *(float2*)(dst + (size_t)(gr + 8) * NCOL + col) = make_float2(acc[nb][2], acc[nb][3]);
    }
}

// ---------------- combine: partials -> g_X and transposed g_XT ---------------
__global__ __launch_bounds__(256) void k_combine() {
    __shared__ float sm[64][65];
    __shared__ float rs[64];
    const int tid = threadIdx.x;
    const int vbase = blockIdx.x * 64;
    if (tid < 64) rs[tid] = g_rowsum[vbase + tid];
    __syncthreads();
#pragma unroll
    for (int j = 0; j < 4; ++j) {
        const int f = tid + j * 256;
        const int r = f >> 4, c = (f & 15) << 2;
        const size_t o = (size_t)(vbase + r) * NCOL + c;
        float4 p0 = *(const float4*)(g_part[0] + o);
        float4 p1 = *(const float4*)(g_part[1] + o);
        const float inv = 1.f / rs[r];
        float4 v;
        v.x = (p0.x + p1.x) * inv; v.y = (p0.y + p1.y) * inv;
        v.z = (p0.z + p1.z) * inv; v.w = (p0.w + p1.w) * inv;
        *(float4*)(g_X + o) = v;
        sm[r][c] = v.x; sm[r][c + 1] = v.y; sm[r][c + 2] = v.z; sm[r][c + 3] = v.w;
    }
    __syncthreads();
    const int col = tid >> 2;
    const int v0 = (tid & 3) << 4;
#pragma unroll
    for (int j = 0; j < 4; ++j) {
        const int v = v0 + j * 4;
        float4 x;
        x.x = sm[v][col]; x.y = sm[v + 1][col]; x.z = sm[v + 2][col]; x.w = sm[v + 3][col];
        *(float4*)(g_XT + (size_t)col * VN + vbase + v) = x;
    }
}

// ---------------- BN stats ---------------------------------------------------
__global__ __launch_bounds__(128) void k_stats(const float* __restrict__ W,
                                               const float* __restrict__ bias) {
    __shared__ float xs[1024];
    const int tid = threadIdx.x;
    const float* __restrict__ Xsrc = g_X + (size_t)4096 * NCOL + (size_t)blockIdx.x * 1024;
#pragma unroll
    for (int j = 0; j < 2; ++j)
        *(float4*)&xs[tid * 8 + j * 4] = *(const float4*)(Xsrc + tid * 8 + j * 4);
    __syncthreads();
    float w[16];
#pragma unroll
    for (int c = 0; c < 16; ++c) w[c] = W[tid * 16 + c];
    const float bb = bias[tid];
    float s = 0.f, ss = 0.f;
    for (int q = 0; q < 64; ++q) {
        const float* xq = &xs[q * 16];
        float y = bb;
#pragma unroll
        for (int c = 0; c < 16; ++c) y = fmaf(w[c], xq[c], y);
        s += y;
        ss = fmaf(y, y, ss);
    }
    g_s1[blockIdx.x * 128 + tid] = s;
    g_s2[blockIdx.x * 128 + tid] = ss;
}

__global__ void k_stats2() {
    const int o = threadIdx.x;
    float s = 0.f, ss = 0.f;
    for (int b2 = 0; b2 < 256; ++b2) { s += g_s1[b2 * 128 + o]; ss += g_s2[b2 * 128 + o]; }
    const float inv = 1.f / 16384.f;
    float mu = s * inv;
    float var = ss * inv - mu * mu;
    g_mu[o] = mu;
    g_rstd[o] = rsqrtf(var + 1e-5f);
}

// ---------------- GLU + BN apply + running max -------------------------------
__global__ __launch_bounds__(128) void k_glu(const float* __restrict__ W,
    const float* __restrict__ bias, const float* __restrict__ gamma,
    const float* __restrict__ beta, float* __restrict__ out, int first)
{
    __shared__ float Wsm[2048], bsm[128], gsm[128], besm[128], musm[128], rsm[128];
    const int tid = threadIdx.x;
    const int n = blockIdx.x * 128 + tid;
    const int b = blockIdx.y;
#pragma unroll
    for (int j = 0; j < 16; ++j) Wsm[tid * 16 + j] = W[tid * 16 + j];
    bsm[tid] = bias[tid]; gsm[tid] = gamma[tid]; besm[tid] = beta[tid];
    musm[tid] = g_mu[tid]; rsm[tid] = g_rstd[tid];
    __syncthreads();

    float xr[16];
    const float* __restrict__ xp = g_X + (size_t)4096 * NCOL + (size_t)n * 64 + b * 16;
#pragma unroll
    for (int j = 0; j < 4; ++j) {
        float4 t = *(const float4*)(xp + j * 4);
        xr[j * 4] = t.x; xr[j * 4 + 1] = t.y; xr[j * 4 + 2] = t.z; xr[j * 4 + 3] = t.w;
    }
    float* op = out + (size_t)b * (64 * 4096) + n;
    for (int f = 0; f < 64; ++f) {
        const float* wl = &Wsm[f * 16];
        const float* wr = &Wsm[(f + 64) * 16];
        float yl = bsm[f], yr = bsm[f + 64];
#pragma unroll
        for (int c = 0; c < 16; ++c) {
            yl = fmaf(wl[c], xr[c], yl);
            yr = fmaf(wr[c], xr[c], yr);
        }
        yl = fmaf(gsm[f] * (yl - musm[f]), rsm[f], besm[f]);
        yr = fmaf(gsm[f + 64] * (yr - musm[f + 64]), rsm[f + 64], besm[f + 64]);
        float val = yl / (1.f + expf(-yr));
        float* po = op + (size_t)f * 4096;
        if (first) *po = val;
        else       *po = fmaxf(*po, val);
    }
}

// ---------------- launch -----------------------------------------------------
extern "C" void kernel_launch(void* const* d_in, const int* in_sizes, int n_in,
                              void* d_out, int out_size)
{
    (void)in_sizes; (void)n_in; (void)out_size;
    const float* adjf = (const float*)d_in[0];
    const float* adjs = (const float*)d_in[1];
    const float* adjm = (const float*)d_in[2];
    const float* data = (const float*)d_in[3];
    const float* alf  = (const float*)d_in[4];
    const float* als  = (const float*)d_in[5];
    const float* gw   = (const float*)d_in[6];
    const float* gb   = (const float*)d_in[7];
    const float* gg   = (const float*)d_in[8];
    const float* gbe  = (const float*)d_in[9];
    float* out = (float*)d_out;

    cudaFuncSetAttribute(k_gemm, cudaFuncAttributeMaxDynamicSharedMemorySize, DSMEM);

    k_alpha<<<1, 1>>>(alf, als);
    k_blend<<<1024, 256>>>(adjf, adjs, adjm);

    for (int h = 0; h < 3; ++h) {
        k_gemm<<<dim3(64, 2), 256, DSMEM>>>(data, h == 0 ? 1 : 0);
        k_combine<<<128, 256>>>();
        k_stats<<<256, 128>>>(gw + h * 2048, gb + h * 128);
        k_stats2<<<1, 128>>>();
        k_glu<<<dim3(32, 4), 128>>>(gw + h * 2048, gb + h * 128,
                                    gg + h * 128, gbe + h * 128, out, h == 0 ? 1 : 0);
    }
}